// round 12
// baseline (speedup 1.0000x reference)
#include <cuda_runtime.h>

// Fixed shapes from setup_inputs
#define LQ 512
#define DD 256
#define FD 512
#define NB 2
#define NH 8
#define DK 64

__device__ float g_A[NB * LQ * FD];
__device__ float g_C[NB * LQ * FD];
__device__ float g_D[NB * LQ * LQ];

typedef unsigned long long u64;

#define FFMA2(d,a,b,c) asm("fma.rn.f32x2 %0,%1,%2,%3;" : "=l"(d) : "l"(a),"l"(b),"l"(c))
#define FADD2(d,a,b)   asm("add.rn.f32x2 %0,%1,%2;"    : "=l"(d) : "l"(a),"l"(b))

__device__ __forceinline__ float2 unpk(u64 p) {
    float lo, hi;
    asm("mov.b64 {%0,%1},%2;" : "=f"(lo), "=f"(hi) : "l"(p));
    return make_float2(lo, hi);
}

#define ABS2_MASK 0x7FFFFFFF7FFFFFFFULL
#define EIGHTH2   0x3E0000003E000000ULL

// ---------------------------------------------------------------------------
// Kernel 1: A = d1 @ W1_top ; C = d0 @ W1_bot + b1   (M=1024, N=512, K=256)
// Tile 64m x 32n, 256 threads, per-thread 4i x 2j (one j-pair), K-chunk 16,
// double-buffered 2-stage pipeline. Grid 16 x 16 x 2 = 512 blocks.
// ---------------------------------------------------------------------------
#define G_AP 132   // dup-A row stride (2*64 + 4)
#define G_BP 36    // B row stride (32 + 4)

__global__ __launch_bounds__(256) void gemm_ac_kernel(
    const float* __restrict__ d1, const float* __restrict__ d0,
    const float* __restrict__ W1, const float* __restrict__ b1)
{
    const int z = blockIdx.z;
    const float* __restrict__ src = z ? d0 : d1;
    const float* __restrict__ W   = W1 + (z ? DD * FD : 0);
    float* dst = z ? g_C : g_A;

    __shared__ __align__(16) float As2[2][16 * G_AP];  // [k][2m] duplicated
    __shared__ __align__(16) float Bs[2][16 * G_BP];   // [k][n]

    const int m0 = blockIdx.y * 64, n0 = blockIdx.x * 32;
    const int t  = threadIdx.x;
    const int jx = t & 15, iy = t >> 4;               // 4i x 2j
    const int rA = t >> 2, qA = t & 3;                // A fill: m-row, k-quad
    const int rB = t >> 4, nB = t & 15;               // B fill: k-row, n-duo

    u64 acc[4] = {};
    float4 va;  float2 vb;

    va = *(const float4*)&src[(m0 + rA) * DD + qA * 4];
    vb = *(const float2*)&W[rB * FD + n0 + nB * 2];

    #pragma unroll 1
    for (int c = 0; c < DD / 16; c++) {
        const int buf = c & 1;
        *(float2*)&As2[buf][(qA * 4 + 0) * G_AP + 2 * rA] = make_float2(va.x, va.x);
        *(float2*)&As2[buf][(qA * 4 + 1) * G_AP + 2 * rA] = make_float2(va.y, va.y);
        *(float2*)&As2[buf][(qA * 4 + 2) * G_AP + 2 * rA] = make_float2(va.z, va.z);
        *(float2*)&As2[buf][(qA * 4 + 3) * G_AP + 2 * rA] = make_float2(va.w, va.w);
        *(float2*)&Bs[buf][rB * G_BP + nB * 2] = vb;
        __syncthreads();

        if (c + 1 < DD / 16) {
            int k0 = (c + 1) * 16;
            va = *(const float4*)&src[(m0 + rA) * DD + k0 + qA * 4];
            vb = *(const float2*)&W[(k0 + rB) * FD + n0 + nB * 2];
        }

        #pragma unroll
        for (int kk = 0; kk < 16; kk++) {
            ulonglong2 aA = *(const ulonglong2*)&As2[buf][kk * G_AP + 8 * iy];
            ulonglong2 aB = *(const ulonglong2*)&As2[buf][kk * G_AP + 8 * iy + 4];
            u64 bp = *(const u64*)&Bs[buf][kk * G_BP + jx * 2];
            FFMA2(acc[0], aA.x, bp, acc[0]);
            FFMA2(acc[1], aA.y, bp, acc[1]);
            FFMA2(acc[2], aB.x, bp, acc[2]);
            FFMA2(acc[3], aB.y, bp, acc[3]);
        }
    }

    u64 bz = 0;
    if (z) bz = *(const u64*)&b1[n0 + jx * 2];

    #pragma unroll
    for (int i = 0; i < 4; i++) {
        u64 r;
        FADD2(r, acc[i], bz);
        *(u64*)&dst[(m0 + iy * 4 + i) * FD + n0 + jx * 2] = r;
    }
}

// ---------------------------------------------------------------------------
// Kernel 2: decisions[b,i,j] = (sum_f relu(A[b,i,f]+C[b,j,f])*w2d[f] + b2d > 0)
//           ? -1e9 : 0
// Tile 32i x 32j, 256 threads, per-thread 2i x 2j (2 pair-units), f-chunk 32
// with chunk-local partials (two-level fp32 order — precision-critical).
// relu exact identity: relu(s)*w = (s+|s|)*(w/2); |s| = and.b64 (alu pipe).
// The 2 dup-A pairs for one thread come from a SINGLE LDS.128.
// Grid 16 x 16 x 2 = 512 blocks.
// ---------------------------------------------------------------------------
#define D_AP 68    // dup-A row stride (2*32 + 4)
#define D_CP 36    // C row stride (32 + 4)

__global__ __launch_bounds__(256) void decisions_kernel(
    const float* __restrict__ W2, const float* __restrict__ b2)
{
    const int b  = blockIdx.z;
    const int i0 = blockIdx.y * 32;
    const int j0 = blockIdx.x * 32;
    const float* __restrict__ Ab = g_A + b * LQ * FD;
    const float* __restrict__ Cb = g_C + b * LQ * FD;

    __shared__ __align__(16) float As2[2][32 * D_AP];  // [f][2i] duplicated
    __shared__ __align__(16) float Cs[2][32 * D_CP];   // [f][j]
    __shared__ __align__(16) float2 ws2[FD];           // {w/2, w/2}

    const int t  = threadIdx.x;
    const int jx = t & 15, iy = t >> 4;               // 2i x 2j
    const int rA = t >> 3, qA = t & 7;                // fills: row, f-quad

    for (int f = t; f < FD; f += 256) {
        float w = 0.5f * (W2[2 * f + 1] - W2[2 * f]);
        ws2[f] = make_float2(w, w);
    }

    u64 acc[2] = {};
    float4 aa, cc;

    aa = *(const float4*)&Ab[(i0 + rA) * FD + qA * 4];
    cc = *(const float4*)&Cb[(j0 + rA) * FD + qA * 4];

    #pragma unroll 1
    for (int c = 0; c < FD / 32; c++) {
        const int buf = c & 1;
        const int f0 = c * 32;
        *(float2*)&As2[buf][(qA * 4 + 0) * D_AP + 2 * rA] = make_float2(aa.x, aa.x);
        *(float2*)&As2[buf][(qA * 4 + 1) * D_AP + 2 * rA] = make_float2(aa.y, aa.y);
        *(float2*)&As2[buf][(qA * 4 + 2) * D_AP + 2 * rA] = make_float2(aa.z, aa.z);
        *(float2*)&As2[buf][(qA * 4 + 3) * D_AP + 2 * rA] = make_float2(aa.w, aa.w);
        Cs[buf][(qA * 4 + 0) * D_CP + rA] = cc.x;
        Cs[buf][(qA * 4 + 1) * D_CP + rA] = cc.y;
        Cs[buf][(qA * 4 + 2) * D_CP + rA] = cc.z;
        Cs[buf][(qA * 4 + 3) * D_CP + rA] = cc.w;
        __syncthreads();

        if (c + 1 < FD / 32) {
            int fn = (c + 1) * 32;
            aa = *(const float4*)&Ab[(i0 + rA) * FD + fn + qA * 4];
            cc = *(const float4*)&Cb[(j0 + rA) * FD + fn + qA * 4];
        }

        u64 accC[2] = {};
        #pragma unroll
        for (int kk = 0; kk < 32; kk++) {
            ulonglong2 aA = *(const ulonglong2*)&As2[buf][kk * D_AP + 4 * iy];
            u64 cp = *(const u64*)&Cs[buf][kk * D_CP + jx * 2];
            u64 wd = *(const u64*)&ws2[f0 + kk];
            u64 s, s2;
            FADD2(s, aA.x, cp);
            s2 = s & ABS2_MASK;
            FADD2(s2, s, s2);                    // 2*relu(s), exact
            FFMA2(accC[0], s2, wd, accC[0]);     // *(w/2), exact scale
            FADD2(s, aA.y, cp);
            s2 = s & ABS2_MASK;
            FADD2(s2, s, s2);
            FFMA2(accC[1], s2, wd, accC[1]);
        }
        FADD2(acc[0], acc[0], accC[0]);
        FADD2(acc[1], acc[1], accC[1]);
    }

    const float b2d = b2[1] - b2[0];
    float* Db = g_D + b * LQ * LQ;
    #pragma unroll
    for (int i = 0; i < 2; i++) {
        float2 p = unpk(acc[i]);
        float2 r = make_float2((p.x + b2d > 0.f) ? -1e9f : 0.f,
                               (p.y + b2d > 0.f) ? -1e9f : 0.f);
        *(float2*)&Db[(i0 + iy * 2 + i) * LQ + j0 + jx * 2] = r;
    }
}

// ---------------------------------------------------------------------------
// Kernel 3: out[b,n,i,j] = dot(q[b,n,i,:], k[b,n,j,:]) * 0.125 + D[b,i,j]
// Tile 64i x 64j, 256 threads, per-thread 4i x 4j, d-chunk 16, 2-stage
// pipeline. Grid 8 x 8 x 16 = 1024 blocks.
// ---------------------------------------------------------------------------
#define A_AP 132
#define A_BP 68

__global__ __launch_bounds__(256) void attn_kernel(
    const float* __restrict__ q, const float* __restrict__ k,
    float* __restrict__ out)
{
    const int bn = blockIdx.z;
    const int b  = bn >> 3;
    const int i0 = blockIdx.y * 64;
    const int j0 = blockIdx.x * 64;
    const float* __restrict__ Q = q + bn * LQ * DK;
    const float* __restrict__ K = k + bn * LQ * DK;

    __shared__ __align__(16) float Qs2[2][16 * A_AP];  // [d][2i] duplicated
    __shared__ __align__(16) float Ks[2][16 * A_BP];   // [d][j]

    const int t  = threadIdx.x;
    const int jx = t & 15, iy = t >> 4;
    const int rA = t >> 2, qA = t & 3;

    u64 acc[4][2] = {};
    float4 vq, vk;

    vq = *(const float4*)&Q[(i0 + rA) * DK + qA * 4];
    vk = *(const float4*)&K[(j0 + rA) * DK + qA * 4];

    #pragma unroll 1
    for (int c = 0; c < DK / 16; c++) {
        const int buf = c & 1;
        *(float2*)&Qs2[buf][(qA * 4 + 0) * A_AP + 2 * rA] = make_float2(vq.x, vq.x);
        *(float2*)&Qs2[buf][(qA * 4 + 1) * A_AP + 2 * rA] = make_float2(vq.y, vq.y);
        *(float2*)&Qs2[buf][(qA * 4 + 2) * A_AP + 2 * rA] = make_float2(vq.z, vq.z);
        *(float2*)&Qs2[buf][(qA * 4 + 3) * A_AP + 2 * rA] = make_float2(vq.w, vq.w);
        Ks[buf][(qA * 4 + 0) * A_BP + rA] = vk.x;
        Ks[buf][(qA * 4 + 1) * A_BP + rA] = vk.y;
        Ks[buf][(qA * 4 + 2) * A_BP + rA] = vk.z;
        Ks[buf][(qA * 4 + 3) * A_BP + rA] = vk.w;
        __syncthreads();

        if (c + 1 < DK / 16) {
            int d0 = (c + 1) * 16;
            vq = *(const float4*)&Q[(i0 + rA) * DK + d0 + qA * 4];
            vk = *(const float4*)&K[(j0 + rA) * DK + d0 + qA * 4];
        }

        #pragma unroll
        for (int kk = 0; kk < 16; kk++) {
            ulonglong2 aA = *(const ulonglong2*)&Qs2[buf][kk * A_AP + 8 * iy];
            ulonglong2 aB = *(const ulonglong2*)&Qs2[buf][kk * A_AP + 8 * iy + 4];
            ulonglong2 bp = *(const ulonglong2*)&Ks[buf][kk * A_BP + jx * 4];
            FFMA2(acc[0][0], aA.x, bp.x, acc[0][0]);
            FFMA2(acc[0][1], aA.x, bp.y, acc[0][1]);
            FFMA2(acc[1][0], aA.y, bp.x, acc[1][0]);
            FFMA2(acc[1][1], aA.y, bp.y, acc[1][1]);
            FFMA2(acc[2][0], aB.x, bp.x, acc[2][0]);
            FFMA2(acc[2][1], aB.x, bp.y, acc[2][1]);
            FFMA2(acc[3][0], aB.y, bp.x, acc[3][0]);
            FFMA2(acc[3][1], aB.y, bp.y, acc[3][1]);
        }
    }

    const float* Db = g_D + b * LQ * LQ;
    float* O = out + bn * LQ * LQ;
    const u64 e2 = EIGHTH2;
    #pragma unroll
    for (int i = 0; i < 4; i++) {
        int row = i0 + iy * 4 + i;
        ulonglong2 dv = *(const ulonglong2*)&Db[row * LQ + j0 + jx * 4];
        ulonglong2 r;
        FFMA2(r.x, acc[i][0], e2, dv.x);
        FFMA2(r.y, acc[i][1], e2, dv.y);
        *(ulonglong2*)&O[row * LQ + j0 + jx * 4] = r;
    }
}

// ---------------------------------------------------------------------------
// Inputs (metadata order): q, k, d0, d1, W1, b1, W2, b2
// ---------------------------------------------------------------------------
extern "C" void kernel_launch(void* const* d_in, const int* in_sizes, int n_in,
                              void* d_out, int out_size)
{
    const float* q  = (const float*)d_in[0];
    const float* k  = (const float*)d_in[1];
    const float* d0 = (const float*)d_in[2];
    const float* d1 = (const float*)d_in[3];
    const float* W1 = (const float*)d_in[4];
    const float* b1 = (const float*)d_in[5];
    const float* W2 = (const float*)d_in[6];
    const float* b2 = (const float*)d_in[7];
    float* out = (float*)d_out;

    (void)in_sizes; (void)n_in; (void)out_size;

    gemm_ac_kernel  <<<dim3(FD / 32, (NB * LQ) / 64, 2),   256>>>(d1, d0, W1, b1);
    decisions_kernel<<<dim3(LQ / 32, LQ / 32, NB),         256>>>(W2, b2);
    attn_kernel     <<<dim3(LQ / 64, LQ / 64, NB * NH),    256>>>(q, k, out);
}

// round 13
// speedup vs baseline: 1.3462x; 1.3462x over previous
#include <cuda_runtime.h>

// Fixed shapes from setup_inputs
#define LQ 512   // sequence length
#define DD 256   // per-tensor feature dim
#define FD 512   // 2*DD (MLP hidden)
#define NB 2     // batch
#define NH 8     // heads
#define DK 64    // head dim

// Scratch (no cudaMalloc allowed)
__device__ float g_A[NB * LQ * FD];   // d1 @ W1[:DD]
__device__ float g_C[NB * LQ * FD];   // d0 @ W1[DD:] + b1
__device__ float g_D[NB * LQ * LQ];   // decisions: 0 or -1e9

typedef unsigned long long u64;

#define FFMA2(d,a,b,c) asm("fma.rn.f32x2 %0,%1,%2,%3;" : "=l"(d) : "l"(a),"l"(b),"l"(c))
#define FADD2(d,a,b)   asm("add.rn.f32x2 %0,%1,%2;"    : "=l"(d) : "l"(a),"l"(b))

__device__ __forceinline__ float2 unpk(u64 p) {
    float lo, hi;
    asm("mov.b64 {%0,%1},%2;" : "=f"(lo), "=f"(hi) : "l"(p));
    return make_float2(lo, hi);
}
__device__ __forceinline__ u64 pk(float lo, float hi) {
    u64 d;
    asm("mov.b64 %0,{%1,%2};" : "=l"(d) : "f"(lo), "f"(hi));
    return d;
}

#define ABS2_MASK 0x7FFFFFFF7FFFFFFFULL   // |x| on both packed halves
#define EIGHTH2   0x3E0000003E000000ULL   // {0.125f, 0.125f}

// ---------------------------------------------------------------------------
// Kernel 1: A = d1 @ W1_top, C = d0 @ W1_bot + b1  — R1 VERBATIM (24.9us).
// M = NB*LQ = 1024 rows, N = FD = 512, K = DD = 256. blockIdx.z selects A/C.
// 64x64 tile, 256 threads, 4x4 per thread, K-chunk 32.
// ---------------------------------------------------------------------------
__global__ __launch_bounds__(256) void gemm_ac_kernel(
    const float* __restrict__ d1, const float* __restrict__ d0,
    const float* __restrict__ W1, const float* __restrict__ b1)
{
    const int z = blockIdx.z;                       // 0 -> A, 1 -> C
    const float* src = z ? d0 : d1;                 // [1024, 256]
    const float* W   = W1 + (z ? (size_t)DD * FD : 0);  // [256, 512]
    float* dst = z ? g_C : g_A;

    __shared__ float As[64][33];   // [m][k], pad breaks stride-128 bank repeat
    __shared__ float Bs[32][64];   // [k][n]

    const int m0 = blockIdx.y * 64;
    const int n0 = blockIdx.x * 64;
    const int t  = threadIdx.x;
    const int tx = t & 15, ty = t >> 4;

    float acc[4][4] = {};

    for (int k0 = 0; k0 < DD; k0 += 32) {
        #pragma unroll
        for (int r = 0; r < 8; r++) {
            int lin = t + r * 256;
            int mm = lin >> 5, kk = lin & 31;
            As[mm][kk] = src[(size_t)(m0 + mm) * DD + k0 + kk];
        }
        #pragma unroll
        for (int r = 0; r < 8; r++) {
            int lin = t + r * 256;
            int kk = lin >> 6, nn = lin & 63;
            Bs[kk][nn] = W[(size_t)(k0 + kk) * FD + n0 + nn];
        }
        __syncthreads();

        #pragma unroll
        for (int kk = 0; kk < 32; kk++) {
            float a[4], b[4];
            #pragma unroll
            for (int i = 0; i < 4; i++) a[i] = As[ty * 4 + i][kk];
            #pragma unroll
            for (int j = 0; j < 4; j++) b[j] = Bs[kk][tx * 4 + j];
            #pragma unroll
            for (int i = 0; i < 4; i++)
                #pragma unroll
                for (int j = 0; j < 4; j++)
                    acc[i][j] = fmaf(a[i], b[j], acc[i][j]);
        }
        __syncthreads();
    }

    #pragma unroll
    for (int i = 0; i < 4; i++) {
        int m = m0 + ty * 4 + i;
        #pragma unroll
        for (int j = 0; j < 4; j++) {
            int n = n0 + tx * 4 + j;
            float v = acc[i][j];
            if (z) v += b1[n];          // fold b1 into C
            dst[(size_t)m * FD + n] = v;
        }
    }
}

// ---------------------------------------------------------------------------
// Kernel 2: decisions[b,i,j] = (sum_f relu(A[b,i,f]+C[b,j,f])*w2d[f] + b2d > 0)
//           ? -1e9 : 0
// R1 tiling (64x64, 256 threads, 4i x 4j, f-chunk 32 with chunk partials)
// but j-PACKED math: C stored transposed [f][j] so a j-pair is one LDS.64;
// a-side broadcast via pk(a,a). relu via exact identity
// relu(s)*w = (s+|s|)*(w/2) — bit-identical (validated R8/R11/R12).
// fma-pipe instrs per kk: 24 (vs 32 scalar); grid 8x8x2 = 128.
// ---------------------------------------------------------------------------
__global__ __launch_bounds__(256) void decisions_kernel(
    const float* __restrict__ W2, const float* __restrict__ b2)
{
    const int b  = blockIdx.z;
    const int i0 = blockIdx.y * 64;
    const int j0 = blockIdx.x * 64;
    const float* Ab = g_A + (size_t)b * LQ * FD;
    const float* Cb = g_C + (size_t)b * LQ * FD;

    __shared__ float As[64][33];                    // [i][f] (R1 layout)
    __shared__ __align__(16) float Cs_T[32][68];    // [f][j] transposed, pad 68
    __shared__ __align__(16) float2 ws2[FD];        // {w/2, w/2}

    const int t  = threadIdx.x;
    const int tx = t & 15, ty = t >> 4;

    for (int f = t; f < FD; f += 256) {
        float w = 0.5f * (W2[2 * f + 1] - W2[2 * f]);
        ws2[f] = make_float2(w, w);
    }

    u64 acc[4][2] = {};

    for (int f0 = 0; f0 < FD; f0 += 32) {
        __syncthreads();
        #pragma unroll
        for (int r = 0; r < 8; r++) {
            int lin = t + r * 256;
            int mm = lin >> 5, ff = lin & 31;
            As[mm][ff] = Ab[(size_t)(i0 + mm) * FD + f0 + ff];
            Cs_T[ff][mm] = Cb[(size_t)(j0 + mm) * FD + f0 + ff];
        }
        __syncthreads();

        u64 accC[4][2] = {};
        #pragma unroll
        for (int ff = 0; ff < 32; ff++) {
            u64 wd = *(const u64*)&ws2[f0 + ff];
            u64 c0 = *(const u64*)&Cs_T[ff][tx * 4];
            u64 c1 = *(const u64*)&Cs_T[ff][tx * 4 + 2];
            #pragma unroll
            for (int i = 0; i < 4; i++) {
                float av = As[ty * 4 + i][ff];
                u64 ad = pk(av, av);
                u64 s, s2;
                FADD2(s, ad, c0);
                s2 = s & ABS2_MASK;                 // |s|
                FADD2(s2, s, s2);                   // 2*relu(s), exact
                FFMA2(accC[i][0], s2, wd, accC[i][0]);   // *(w/2): exact product
                FADD2(s, ad, c1);
                s2 = s & ABS2_MASK;
                FADD2(s2, s, s2);
                FFMA2(accC[i][1], s2, wd, accC[i][1]);
            }
        }
        #pragma unroll
        for (int i = 0; i < 4; i++) {
            FADD2(acc[i][0], acc[i][0], accC[i][0]);
            FADD2(acc[i][1], acc[i][1], accC[i][1]);
        }
    }

    const float b2d = b2[1] - b2[0];
    float* Db = g_D + (size_t)b * LQ * LQ;
    #pragma unroll
    for (int i = 0; i < 4; i++) {
        float2 p0 = unpk(acc[i][0]), p1 = unpk(acc[i][1]);
        int ii = i0 + ty * 4 + i;
        float4 r = make_float4(
            (p0.x + b2d > 0.f) ? -1e9f : 0.f, (p0.y + b2d > 0.f) ? -1e9f : 0.f,
            (p1.x + b2d > 0.f) ? -1e9f : 0.f, (p1.y + b2d > 0.f) ? -1e9f : 0.f);
        *(float4*)&Db[(size_t)ii * LQ + j0 + tx * 4] = r;
    }
}

// ---------------------------------------------------------------------------
// Kernel 3: out[b,n,i,j] = dot(q[b,n,i,:], k[b,n,j,:]) / 8 + D[b,i,j]
// R1 tiling (64x64 per (b,n), full d=64 staged, 4i x 4j) but j-PACKED:
// K stored transposed [d][j]; a-side broadcast via pk(a,a).
// fma-pipe instrs per dd: 8 FFMA2 (vs 16 FFMA scalar). Grid 8x8x16 = 1024.
// ---------------------------------------------------------------------------
__global__ __launch_bounds__(256) void attn_kernel(
    const float* __restrict__ q, const float* __restrict__ k,
    float* __restrict__ out)
{
    const int bn = blockIdx.z;          // 0..15 = b*NH + n
    const int b  = bn >> 3;
    const int i0 = blockIdx.y * 64;
    const int j0 = blockIdx.x * 64;
    const float* Q = q + (size_t)bn * LQ * DK;
    const float* K = k + (size_t)bn * LQ * DK;

    __shared__ float Qs[64][65];                    // [i][d] (R1 layout)
    __shared__ __align__(16) float Ks_T[64][68];    // [d][j] transposed

    const int t  = threadIdx.x;
    const int tx = t & 15, ty = t >> 4;

    #pragma unroll
    for (int r = 0; r < 16; r++) {
        int lin = t + r * 256;
        int ii = lin >> 6, dd = lin & 63;
        Qs[ii][dd] = Q[(size_t)(i0 + ii) * DK + dd];
        Ks_T[dd][ii] = K[(size_t)(j0 + ii) * DK + dd];
    }
    __syncthreads();

    u64 acc[4][2] = {};
    #pragma unroll 16
    for (int dd = 0; dd < DK; dd++) {
        u64 c0 = *(const u64*)&Ks_T[dd][tx * 4];
        u64 c1 = *(const u64*)&Ks_T[dd][tx * 4 + 2];
        #pragma unroll
        for (int i = 0; i < 4; i++) {
            float av = Qs[ty * 4 + i][dd];
            u64 ad = pk(av, av);
            FFMA2(acc[i][0], ad, c0, acc[i][0]);
            FFMA2(acc[i][1], ad, c1, acc[i][1]);
        }
    }

    const float* Db = g_D + (size_t)b * LQ * LQ;
    float* O = out + (size_t)bn * LQ * LQ;
    const u64 e2 = EIGHTH2;
    #pragma unroll
    for (int i = 0; i < 4; i++) {
        int row = i0 + ty * 4 + i;
        ulonglong2 dv = *(const ulonglong2*)&Db[(size_t)row * LQ + j0 + tx * 4];
        ulonglong2 r;
        FFMA2(r.x, acc[i][0], e2, dv.x);            // qk*0.125 + D, packed
        FFMA2(r.y, acc[i][1], e2, dv.y);
        *(ulonglong2*)&O[(size_t)row * LQ + j0 + tx * 4] = r;
    }
}

// ---------------------------------------------------------------------------
// Inputs (metadata order): q, k, d0, d1, W1, b1, W2, b2
// ---------------------------------------------------------------------------
extern "C" void kernel_launch(void* const* d_in, const int* in_sizes, int n_in,
                              void* d_out, int out_size)
{
    const float* q  = (const float*)d_in[0];   // [2,8,512,64]
    const float* k  = (const float*)d_in[1];   // [2,8,512,64]
    const float* d0 = (const float*)d_in[2];   // [2,512,256]
    const float* d1 = (const float*)d_in[3];   // [2,512,256]
    const float* W1 = (const float*)d_in[4];   // [512,512]
    const float* b1 = (const float*)d_in[5];   // [512]
    const float* W2 = (const float*)d_in[6];   // [512,2]
    const float* b2 = (const float*)d_in[7];   // [2]
    float* out = (float*)d_out;                // [2,8,512,512]

    (void)in_sizes; (void)n_in; (void)out_size;

    gemm_ac_kernel  <<<dim3(FD / 64, (NB * LQ) / 64, 2),   256>>>(d1, d0, W1, b1);
    decisions_kernel<<<dim3(LQ / 64, LQ / 64, NB),         256>>>(W2, b2);
    attn_kernel     <<<dim3(LQ / 64, LQ / 64, NB * NH),    256>>>(q, k, out);
}